// round 16
// baseline (speedup 1.0000x reference)
#include <cuda_runtime.h>
#include <cuda_fp16.h>
#include <cstdint>
#include <cstring>
#include <math.h>

#define B_  2
#define N_  2048
#define D_  1024
#define H_  8
#define QH_ 16
#define DH_ 64
#define ROWS (B_*N_)   // 4096

// ---------------- scratch (device globals; no allocs) ----------------
__device__ __half g_xnh[(size_t)ROWS * D_];           // rmsnormed tokens (fp16)
__device__ __half g_qprojh[(size_t)ROWS * 1024];      // x @ Wq (fp16)
__device__ __half g_kvh[(size_t)ROWS * 1024];         // x @ Wkv (fp16)
__device__ __half g_qh[(size_t)B_ * QH_ * N_ * DH_];  // [b][qh][n][dh] fp16
__device__ __half g_kh[(size_t)B_ * H_  * N_ * DH_];  // [b][h][n][dh] fp16
__device__ __half g_vh[(size_t)B_ * H_  * N_ * DH_];  // [b][h][n][dh] fp16
__device__ __half g_oh[(size_t)B_ * QH_ * N_ * DH_];  // per-qhead attn out (fp16)
__device__ __half g_och[(size_t)ROWS * (H_ * DH_)];   // group-summed (fp16)
__device__ __half g_Wqh [(size_t)1024 * 1024];        // fp16 Wq  [k][n]
__device__ __half g_Wkvh[(size_t)1024 * 1024];        // fp16 Wkv [k][n]
__device__ __half g_Woh [(size_t)512 * 1024];         // fp16 Wout[k][n]

// ---------------- helpers ----------------
__device__ __forceinline__ uint32_t smem_u32(const void* p) {
    uint32_t a;
    asm("{ .reg .u64 t; cvta.to.shared.u64 t, %1; cvt.u32.u64 %0, t; }" : "=r"(a) : "l"(p));
    return a;
}
__device__ __forceinline__ uint32_t h2u(__half2 v) {
    uint32_t u;
    memcpy(&u, &v, 4);
    return u;
}
__device__ __forceinline__ void cpa16(uint32_t dst, const void* src) {
    asm volatile("cp.async.ca.shared.global [%0], [%1], 16;" :: "r"(dst), "l"(src));
}
#define CP_COMMIT() asm volatile("cp.async.commit_group;" ::: "memory")
#define CP_WAIT(n)  asm volatile("cp.async.wait_group %0;" :: "n"(n) : "memory")

__device__ __forceinline__ void mmah(float* d, const uint32_t* a, const uint32_t* b) {
    asm volatile("mma.sync.aligned.m16n8k16.row.col.f32.f16.f16.f32 "
                 "{%0,%1,%2,%3}, {%4,%5,%6,%7}, {%8,%9}, {%0,%1,%2,%3};"
                 : "+f"(d[0]), "+f"(d[1]), "+f"(d[2]), "+f"(d[3])
                 : "r"(a[0]), "r"(a[1]), "r"(a[2]), "r"(a[3]),
                   "r"(b[0]), "r"(b[1]));
}
__device__ __forceinline__ void ldsm_x4(uint32_t* r, uint32_t addr) {
    asm volatile("ldmatrix.sync.aligned.m8n8.x4.shared.b16 {%0,%1,%2,%3}, [%4];"
                 : "=r"(r[0]), "=r"(r[1]), "=r"(r[2]), "=r"(r[3]) : "r"(addr));
}
__device__ __forceinline__ void ldsm_x4t(uint32_t* r, uint32_t addr) {
    asm volatile("ldmatrix.sync.aligned.m8n8.x4.trans.shared.b16 {%0,%1,%2,%3}, [%4];"
                 : "=r"(r[0]), "=r"(r[1]), "=r"(r[2]), "=r"(r[3]) : "r"(addr));
}
__device__ __forceinline__ void ldsm_x2t(uint32_t* r, uint32_t addr) {
    asm volatile("ldmatrix.sync.aligned.m8n8.x2.trans.shared.b16 {%0,%1}, [%2];"
                 : "=r"(r[0]), "=r"(r[1]) : "r"(addr));
}
// P = exp(6.25 * tanh(s/50)) via MUFU.TANH + MUFU.EX2 (2 MUL + 2 MUFU).
__device__ __forceinline__ float softcap_exp(float s) {
    float t;
    asm("tanh.approx.f32 %0, %1;" : "=f"(t) : "f"(s * 0.02f));
    float e;
    asm("ex2.approx.f32 %0, %1;" : "=f"(e) : "f"(t * 9.0168440055f));
    return e;
}
// epilogue store: fp32 or fp16
__device__ __forceinline__ void st2(float* C, size_t off, float x, float y) {
    *(float2*)(C + off) = make_float2(x, y);
}
__device__ __forceinline__ void st2(__half* C, size_t off, float x, float y) {
    *(__half2*)(C + off) = __floats2half2_rn(x, y);
}

// ---------------- 1) fused RMSNorm->fp16 + weight fp32->fp16 ----------------
__global__ __launch_bounds__(256) void k_pre(const float* __restrict__ x,
                                             const float* __restrict__ w,
                                             const float4* __restrict__ Wq,
                                             const float4* __restrict__ Wkv,
                                             const float4* __restrict__ Wo) {
    if (blockIdx.x < 4096) {
        int row = blockIdx.x;
        const float4* xr = (const float4*)(x + (size_t)row * D_);
        float4 xv = xr[threadIdx.x];
        float ss = xv.x*xv.x + xv.y*xv.y + xv.z*xv.z + xv.w*xv.w;
        #pragma unroll
        for (int o = 16; o; o >>= 1) ss += __shfl_xor_sync(0xffffffffu, ss, o);
        __shared__ float sred[8];
        int wid = threadIdx.x >> 5, lid = threadIdx.x & 31;
        if (lid == 0) sred[wid] = ss;
        __syncthreads();
        if (wid == 0) {
            float v = (lid < 8) ? sred[lid] : 0.0f;
            #pragma unroll
            for (int o = 4; o; o >>= 1) v += __shfl_xor_sync(0xffffffffu, v, o);
            if (lid == 0) sred[0] = v;
        }
        __syncthreads();
        float s = rsqrtf(sred[0] * (1.0f / D_) + 1.192092896e-7f);
        float4 wv = ((const float4*)w)[threadIdx.x];
        __half2* dst = (__half2*)(g_xnh + (size_t)row * D_ + threadIdx.x * 4);
        dst[0] = __floats2half2_rn(xv.x * s * wv.x, xv.y * s * wv.y);
        dst[1] = __floats2half2_rn(xv.z * s * wv.z, xv.w * s * wv.w);
    } else {
        int i = (blockIdx.x - 4096) * 256 + threadIdx.x;   // < 655360
        const float4* src; __half2* dst; int j;
        if (i < 262144)      { src = Wq;  dst = (__half2*)g_Wqh;  j = i; }
        else if (i < 524288) { src = Wkv; dst = (__half2*)g_Wkvh; j = i - 262144; }
        else                 { src = Wo;  dst = (__half2*)g_Woh;  j = i - 524288; }
        float4 v = src[j];
        dst[2 * j]     = __floats2half2_rn(v.x, v.y);
        dst[2 * j + 1] = __floats2half2_rn(v.z, v.w);
    }
}

// ---------------- 2) fp16 mma GEMM, 3-stage cp.async pipeline ----------------
#define HAS 40
#define HBS 136
#define HASZ (128 * HAS)
#define HBSZ (32 * HBS)
#define HSTG (HASZ + HBSZ)          // 9472 halves / stage
#define GSM  (3 * HSTG * 2)         // 56832 bytes dynamic

template <int NX0, typename T>
__global__ __launch_bounds__(256) void k_gemmh(const __half* __restrict__ A,
                                               const __half* __restrict__ W0,
                                               const __half* __restrict__ W1,
                                               T* __restrict__ C0,
                                               T* __restrict__ C1, int K) {
    extern __shared__ __half hs[];
    const int t = threadIdx.x, wid = t >> 5, lane = t & 31;
    const int wm = wid >> 2, wn = wid & 3;
    const int r = lane >> 2, cq = lane & 3;
    const int m0 = blockIdx.y * 128;
    const __half* W; T* C; int n0;
    if ((int)blockIdx.x < NX0) { W = W0; C = C0; n0 = blockIdx.x * 128; }
    else                       { W = W1; C = C1; n0 = (blockIdx.x - NX0) * 128; }
    const uint32_t sb = smem_u32(hs);

    const int qa0 = t, qa1 = t + 256;
    const int ar0 = qa0 >> 2, ac0 = (qa0 & 3) * 8;
    const int ar1 = qa1 >> 2, ac1 = (qa1 & 3) * 8;
    const int br0 = qa0 >> 4, bc0 = (qa0 & 15) * 8;
    const int br1 = qa1 >> 4, bc1 = (qa1 & 15) * 8;

    const int lrow = lane & 7, lt = lane >> 3;
    const int aR = (lt & 1) * 8 + lrow;
    const int aC = (lt >> 1) * 8;
    const int lb = lane & 15, bt = lb >> 3, brw = lb & 7;

    float d[4][4][4];
    #pragma unroll
    for (int i = 0; i < 4; i++)
        #pragma unroll
        for (int j = 0; j < 4; j++)
            #pragma unroll
            for (int v = 0; v < 4; v++) d[i][j][v] = 0.0f;

    const int nc = K >> 5;

    #define LOAD_STAGE(s, c) do { \
        uint32_t ab = sb + (s) * (HSTG * 2); \
        uint32_t bb = ab + HASZ * 2; \
        int k0 = (c) << 5; \
        cpa16(ab + (ar0 * HAS + ac0) * 2, A + (size_t)(m0 + ar0) * K + k0 + ac0); \
        cpa16(ab + (ar1 * HAS + ac1) * 2, A + (size_t)(m0 + ar1) * K + k0 + ac1); \
        cpa16(bb + (br0 * HBS + bc0) * 2, W + (size_t)(k0 + br0) * 1024 + n0 + bc0); \
        cpa16(bb + (br1 * HBS + bc1) * 2, W + (size_t)(k0 + br1) * 1024 + n0 + bc1); \
        CP_COMMIT(); \
    } while (0)

    LOAD_STAGE(0, 0);
    LOAD_STAGE(1, 1);

    for (int c = 0; c < nc; c++) {
        if (c == nc - 1) { CP_WAIT(0); } else { CP_WAIT(1); }
        __syncthreads();
        if (c + 2 < nc) LOAD_STAGE((c + 2) % 3, c + 2);

        uint32_t ab = sb + (c % 3) * (HSTG * 2);
        uint32_t bb = ab + HASZ * 2;
        #pragma unroll
        for (int ks = 0; ks < 2; ks++) {
            uint32_t a[4][4], b[4][2];
            #pragma unroll
            for (int mt = 0; mt < 4; mt++)
                ldsm_x4(a[mt], ab + ((wm * 64 + mt * 16 + aR) * HAS + ks * 16 + aC) * 2);
            #pragma unroll
            for (int nt = 0; nt < 4; nt++)
                ldsm_x2t(b[nt], bb + ((ks * 16 + bt * 8 + brw) * HBS + wn * 32 + nt * 8) * 2);
            #pragma unroll
            for (int mt = 0; mt < 4; mt++)
                #pragma unroll
                for (int nt = 0; nt < 4; nt++) mmah(d[mt][nt], a[mt], b[nt]);
        }
    }

    #pragma unroll
    for (int mt = 0; mt < 4; mt++) {
        int row = m0 + wm * 64 + mt * 16 + r;
        #pragma unroll
        for (int nt = 0; nt < 4; nt++) {
            int col = n0 + wn * 32 + nt * 8 + 2 * cq;
            st2(C, (size_t)row * 1024 + col, d[mt][nt][0], d[mt][nt][1]);
            st2(C, (size_t)(row + 8) * 1024 + col, d[mt][nt][2], d[mt][nt][3]);
        }
    }
    #undef LOAD_STAGE
}

// ---------------- 3) q/k head norm + v copy: uint4 lanes, 8-lane reduce ----------------
__global__ __launch_bounds__(256) void k_qknorm(const float* __restrict__ q_gamma,
                                                const float* __restrict__ k_gamma) {
    int warp = threadIdx.x >> 5, lane = threadIdx.x & 31;
    int sub = lane >> 3, e8 = (lane & 7) * 8;
    int vec = (blockIdx.x * 8 + warp) * 4 + sub;   // < 98304
    if (vec < 65536) {
        int row = vec >> 4, qh = vec & 15;
        uint4 raw = *(const uint4*)(g_qprojh + (size_t)row * 1024 + qh * 64 + e8);
        __half2 hv[4];
        memcpy(hv, &raw, 16);
        float2 f[4];
        float ss = 0.0f;
        #pragma unroll
        for (int j = 0; j < 4; j++) {
            f[j] = __half22float2(hv[j]);
            ss += f[j].x * f[j].x + f[j].y * f[j].y;
        }
        ss += __shfl_xor_sync(0xffffffffu, ss, 1);
        ss += __shfl_xor_sync(0xffffffffu, ss, 2);
        ss += __shfl_xor_sync(0xffffffffu, ss, 4);
        float inv = 1.0f / fmaxf(sqrtf(ss), 1e-12f);
        float4 g0 = *(const float4*)(q_gamma + qh * 64 + e8);
        float4 g1 = *(const float4*)(q_gamma + qh * 64 + e8 + 4);
        __half2 out[4];
        out[0] = __floats2half2_rn(f[0].x * inv * (g0.x + 1.0f) * 8.0f,
                                   f[0].y * inv * (g0.y + 1.0f) * 8.0f);
        out[1] = __floats2half2_rn(f[1].x * inv * (g0.z + 1.0f) * 8.0f,
                                   f[1].y * inv * (g0.w + 1.0f) * 8.0f);
        out[2] = __floats2half2_rn(f[2].x * inv * (g1.x + 1.0f) * 8.0f,
                                   f[2].y * inv * (g1.y + 1.0f) * 8.0f);
        out[3] = __floats2half2_rn(f[3].x * inv * (g1.z + 1.0f) * 8.0f,
                                   f[3].y * inv * (g1.w + 1.0f) * 8.0f);
        int b = row >> 11, n = row & 2047;
        uint4 packed;
        memcpy(&packed, out, 16);
        *(uint4*)(g_qh + ((((size_t)b * QH_ + qh) * N_ + n) * DH_) + e8) = packed;
    } else {
        int v2 = vec - 65536;
        int row = v2 >> 3, h = v2 & 7;
        const __half* base = g_kvh + (size_t)row * 1024 + h * 64 + e8;
        uint4 kraw = *(const uint4*)base;
        uint4 vraw = *(const uint4*)(base + 512);
        __half2 hv[4];
        memcpy(hv, &kraw, 16);
        float2 f[4];
        float ss = 0.0f;
        #pragma unroll
        for (int j = 0; j < 4; j++) {
            f[j] = __half22float2(hv[j]);
            ss += f[j].x * f[j].x + f[j].y * f[j].y;
        }
        ss += __shfl_xor_sync(0xffffffffu, ss, 1);
        ss += __shfl_xor_sync(0xffffffffu, ss, 2);
        ss += __shfl_xor_sync(0xffffffffu, ss, 4);
        float inv = 1.0f / fmaxf(sqrtf(ss), 1e-12f);
        float4 g0 = *(const float4*)(k_gamma + h * 64 + e8);
        float4 g1 = *(const float4*)(k_gamma + h * 64 + e8 + 4);
        __half2 out[4];
        out[0] = __floats2half2_rn(f[0].x * inv * (g0.x + 1.0f) * 8.0f,
                                   f[0].y * inv * (g0.y + 1.0f) * 8.0f);
        out[1] = __floats2half2_rn(f[1].x * inv * (g0.z + 1.0f) * 8.0f,
                                   f[1].y * inv * (g0.w + 1.0f) * 8.0f);
        out[2] = __floats2half2_rn(f[2].x * inv * (g1.x + 1.0f) * 8.0f,
                                   f[2].y * inv * (g1.y + 1.0f) * 8.0f);
        out[3] = __floats2half2_rn(f[3].x * inv * (g1.z + 1.0f) * 8.0f,
                                   f[3].y * inv * (g1.w + 1.0f) * 8.0f);
        int b = row >> 11, n = row & 2047;
        size_t dst = (((size_t)b * H_ + h) * N_ + n) * DH_ + e8;
        uint4 packed;
        memcpy(&packed, out, 16);
        *(uint4*)(g_kh + dst) = packed;
        *(uint4*)(g_vh + dst) = vraw;
    }
}

// ---------------- 4) causal attention: 32 rows x 32 keys / warp ----------------
// CTA = 128 threads, 4 warps, 128 q-rows; key-tiles of 32.
// K/V fragments reused across 2 row-blocks -> smem reads per row*key halved.
// smem: 4 regions of 4608 halves (stride 72) = 36864 B.
// Q (128x64) staged through regions 0-1, fragments hoisted, then regions
// become K0|V0|K1|V1. Per-warp causal trip: warp wm active for jt <= 4*it+wm.
#define AQS 72
#define T46 4608
#define ATT3_SMEM (4 * T46 * 2)

__global__ __launch_bounds__(128) void k_attn3() {
    extern __shared__ __half sh[];
    const uint32_t sb = smem_u32(sh);

    int bqh = blockIdx.y;                       // b*16 + qh
    int it  = gridDim.x - 1 - blockIdx.x;       // biggest tiles first (16 q-tiles)
    int b = bqh >> 4, qh = bqh & 15, h = qh >> 1;

    const __half* Qg = g_qh + (((size_t)bqh) * N_ + it * 128) * DH_;
    const __half* Kg = g_kh + ((size_t)(b * H_ + h)) * N_ * DH_;
    const __half* Vg = g_vh + ((size_t)(b * H_ + h)) * N_ * DH_;

    const int t = threadIdx.x, wm = t >> 5, lane = t & 31;
    const int r = lane >> 2, cq = lane & 3;
    const int lrow = lane & 7, lt = lane >> 3;
    const int aR = (lt & 1) * 8 + lrow, aC = (lt >> 1) * 8;
    const int pn = lt >> 1, pb = (lt & 1) * 8;   // paired-x4 geometry

    // ---- prologue: Q (128x64) through regions 0-1, hoist fragments ----
    #pragma unroll
    for (int rep = 0; rep < 8; rep++) {
        int slot = rep * 128 + t;
        int i = slot >> 3, d8 = (slot & 7) * 8;
        *(uint4*)&sh[i * AQS + d8] = *(const uint4*)(Qg + i * 64 + d8);
    }
    __syncthreads();
    uint32_t qa[2][4][4];                        // [mblock][ks][frag]
    #pragma unroll
    for (int m = 0; m < 2; m++)
        #pragma unroll
        for (int ks = 0; ks < 4; ks++)
            ldsm_x4(qa[m][ks], sb + ((wm * 32 + m * 16 + aR) * AQS + ks * 16 + aC) * 2);
    __syncthreads();   // all warps done reading Q; regions reusable

    // K stage s -> region 2s, V stage s -> region 2s+1 (32 rows each)
    #define LOADKV(s, jt_) do { \
        uint32_t kb_ = sb + (2 * (s)) * T46 * 2; \
        uint32_t vb_ = sb + (2 * (s) + 1) * T46 * 2; \
        _Pragma("unroll") \
        for (int rep = 0; rep < 2; rep++) { \
            int slot = rep * 128 + t; \
            int j = slot >> 3, d8 = (slot & 7) * 8; \
            cpa16(kb_ + (j * AQS + d8) * 2, Kg + (size_t)((jt_) * 32 + j) * 64 + d8); \
            cpa16(vb_ + (j * AQS + d8) * 2, Vg + (size_t)((jt_) * 32 + j) * 64 + d8); \
        } \
        CP_COMMIT(); \
    } while (0)

    LOADKV(0, 0);

    const uint32_t ONE2 = 0x3C003C00u;          // half2(1,1)
    uint32_t ones[2] = {ONE2, ONE2};

    float o[2][8][4];                            // [mblock][dh-tile][frag]
    #pragma unroll
    for (int m = 0; m < 2; m++)
        #pragma unroll
        for (int nt = 0; nt < 8; nt++)
            #pragma unroll
            for (int v = 0; v < 4; v++) o[m][nt][v] = 0.0f;
    float o9[2][4] = {{0.f,0.f,0.f,0.f},{0.f,0.f,0.f,0.f}};

    const int ntile = 4 * it + 4;               // key-tiles needed by warp 3
    const int mytile = 4 * it + wm;             // last tile this warp computes

    for (int jt = 0; jt < ntile; jt++) {
        int s = jt & 1;
        CP_WAIT(0);
        __syncthreads();       // stage s visible; prior reads of s^1 done
        if (jt + 1 < ntile) LOADKV(s ^ 1, jt + 1);

        if (jt <= mytile) {
            uint32_t kb = sb + (2 * s) * T46 * 2;
            uint32_t vb = sb + (2 * s + 1) * T46 * 2;

            // ---- S = Q K^T : K fragments shared across both row-blocks ----
            float dS[2][4][4];
            #pragma unroll
            for (int m = 0; m < 2; m++)
                #pragma unroll
                for (int nt = 0; nt < 4; nt++)
                    #pragma unroll
                    for (int v = 0; v < 4; v++) dS[m][nt][v] = 0.0f;

            #pragma unroll
            for (int ks = 0; ks < 4; ks++) {
                #pragma unroll
                for (int np = 0; np < 2; np++) {     // n-tile pair 2np, 2np+1
                    uint32_t kr[4];
                    ldsm_x4(kr, kb + (((2 * np + pn) * 8 + lrow) * AQS + ks * 16 + pb) * 2);
                    #pragma unroll
                    for (int m = 0; m < 2; m++) {
                        mmah(dS[m][2 * np],     qa[m][ks], kr);
                        mmah(dS[m][2 * np + 1], qa[m][ks], kr + 2);
                    }
                }
            }

            // ---- softcap+exp+mask -> pack P into PV A-fragments ----
            uint32_t ah[2][2][4];                    // [mblock][kchunk][frag]
            if (jt == mytile) {
                int i0g = it * 128 + wm * 32, j0g = jt * 32;
                #pragma unroll
                for (int m = 0; m < 2; m++)
                    #pragma unroll
                    for (int nt = 0; nt < 4; nt++) {
                        int colb = j0g + nt * 8 + 2 * cq;
                        int rr = i0g + m * 16 + r;
                        float p0 = (colb     <= rr)     ? softcap_exp(dS[m][nt][0]) : 0.0f;
                        float p1 = (colb + 1 <= rr)     ? softcap_exp(dS[m][nt][1]) : 0.0f;
                        float p2 = (colb     <= rr + 8) ? softcap_exp(dS[m][nt][2]) : 0.0f;
                        float p3 = (colb + 1 <= rr + 8) ? softcap_exp(dS[m][nt][3]) : 0.0f;
                        int kc = nt >> 1, hi = (nt & 1) * 2;
                        ah[m][kc][hi]     = h2u(__floats2half2_rn(p0, p1));
                        ah[m][kc][hi + 1] = h2u(__floats2half2_rn(p2, p3));
                    }
            } else {
                #pragma unroll
                for (int m = 0; m < 2; m++)
                    #pragma unroll
                    for (int nt = 0; nt < 4; nt++) {
                        float p0 = softcap_exp(dS[m][nt][0]);
                        float p1 = softcap_exp(dS[m][nt][1]);
                        float p2 = softcap_exp(dS[m][nt][2]);
                        float p3 = softcap_exp(dS[m][nt][3]);
                        int kc = nt >> 1, hi = (nt & 1) * 2;
                        ah[m][kc][hi]     = h2u(__floats2half2_rn(p0, p1));
                        ah[m][kc][hi + 1] = h2u(__floats2half2_rn(p2, p3));
                    }
            }

            // ---- O += P V : V fragments shared across both row-blocks ----
            #pragma unroll
            for (int kc = 0; kc < 2; kc++) {
                #pragma unroll
                for (int vp = 0; vp < 4; vp++) {     // dh-tile pair 2vp, 2vp+1
                    uint32_t vr[4];
                    ldsm_x4t(vr, vb + ((kc * 16 + pb + lrow) * AQS + (2 * vp + pn) * 8) * 2);
                    #pragma unroll
                    for (int m = 0; m < 2; m++) {
                        mmah(o[m][2 * vp],     ah[m][kc], vr);
                        mmah(o[m][2 * vp + 1], ah[m][kc], vr + 2);
                    }
                }
                mmah(o9[0], ah[0][kc], ones);
                mmah(o9[1], ah[1][kc], ones);
            }
        }
    }

    #pragma unroll
    for (int m = 0; m < 2; m++) {
        float inv  = 1.0f / o9[m][0];
        float inv8 = 1.0f / o9[m][2];
        __half* Og = g_oh + (((size_t)bqh) * N_ + it * 128 + wm * 32 + m * 16 + r) * DH_;
        #pragma unroll
        for (int nt = 0; nt < 8; nt++) {
            int colb = nt * 8 + 2 * cq;
            *(__half2*)(Og + colb) =
                __floats2half2_rn(o[m][nt][0] * inv, o[m][nt][1] * inv);
            *(__half2*)(Og + (size_t)8 * 64 + colb) =
                __floats2half2_rn(o[m][nt][2] * inv8, o[m][nt][3] * inv8);
        }
    }
    #undef LOADKV
}

// ---------------- 5) group-sum combine (fp16 in/out, 8 halves/thread) ----------------
__global__ __launch_bounds__(256) void k_combine() {
    int s8 = blockIdx.x * 256 + threadIdx.x;   // 8-half slot, < 262144
    int col = (s8 & 63) * 8;
    int row = s8 >> 6;
    int h = col >> 6, dh = col & 63;
    int b = row >> 11, n = row & 2047;
    const __half* o1 = g_oh + ((((size_t)b * QH_ + 2 * h) * N_ + n) * DH_ + dh);
    const __half* o2 = o1 + (size_t)N_ * DH_;
    uint4 araw = *(const uint4*)o1, craw = *(const uint4*)o2;
    __half2 a[4], c[4], y[4];
    memcpy(a, &araw, 16);
    memcpy(c, &craw, 16);
    #pragma unroll
    for (int j = 0; j < 4; j++) {
        float2 fa = __half22float2(a[j]), fc = __half22float2(c[j]);
        y[j] = __floats2half2_rn(fa.x + fc.x, fa.y + fc.y);
    }
    uint4 packed;
    memcpy(&packed, y, 16);
    *(uint4*)(g_och + (size_t)row * 512 + col) = packed;
}

// ---------------- launch ----------------
extern "C" void kernel_launch(void* const* d_in, const int* in_sizes, int n_in,
                              void* d_out, int out_size) {
    const float* tokens  = (const float*)d_in[0];
    const float* norm_w  = (const float*)d_in[1];
    const float* Wq      = (const float*)d_in[2];
    const float* Wkv     = (const float*)d_in[3];
    const float* Wout    = (const float*)d_in[4];
    const float* q_gamma = (const float*)d_in[5];
    const float* k_gamma = (const float*)d_in[6];
    float* out = (float*)d_out;

    static __half *Wqh_p = nullptr, *Wkvh_p = nullptr, *Woh_p = nullptr;
    static __half *xnh_p = nullptr, *och_p = nullptr, *qprojh_p = nullptr, *kvh_p = nullptr;
    if (!Wqh_p) {   // first call is the non-captured correctness run
        cudaGetSymbolAddress((void**)&Wqh_p, g_Wqh);
        cudaGetSymbolAddress((void**)&Wkvh_p, g_Wkvh);
        cudaGetSymbolAddress((void**)&Woh_p, g_Woh);
        cudaGetSymbolAddress((void**)&xnh_p, g_xnh);
        cudaGetSymbolAddress((void**)&och_p, g_och);
        cudaGetSymbolAddress((void**)&qprojh_p, g_qprojh);
        cudaGetSymbolAddress((void**)&kvh_p, g_kvh);
        cudaFuncSetAttribute(k_attn3, cudaFuncAttributeMaxDynamicSharedMemorySize, ATT3_SMEM);
        cudaFuncSetAttribute(k_gemmh<8, __half>, cudaFuncAttributeMaxDynamicSharedMemorySize, GSM);
        cudaFuncSetAttribute(k_gemmh<8, float>, cudaFuncAttributeMaxDynamicSharedMemorySize, GSM);
    }

    k_pre<<<6656, 256>>>(tokens, norm_w, (const float4*)Wq,
                         (const float4*)Wkv, (const float4*)Wout);
    k_gemmh<8, __half><<<dim3(16, 32), 256, GSM>>>(xnh_p, Wqh_p, Wkvh_p, qprojh_p, kvh_p, 1024);
    k_qknorm<<<3072, 256>>>(q_gamma, k_gamma);
    k_attn3<<<dim3(16, 32), 128, ATT3_SMEM>>>();
    k_combine<<<1024, 256>>>();
    k_gemmh<8, float><<<dim3(8, 32), 256, GSM>>>(och_p, Woh_p, Woh_p, out, out, 512);
}

// round 17
// speedup vs baseline: 1.0773x; 1.0773x over previous
#include <cuda_runtime.h>
#include <cuda_fp16.h>
#include <cstdint>
#include <cstring>
#include <math.h>

#define B_  2
#define N_  2048
#define D_  1024
#define H_  8
#define QH_ 16
#define DH_ 64
#define ROWS (B_*N_)   // 4096

// ---------------- scratch (device globals; no allocs) ----------------
__device__ __half g_xnh[(size_t)ROWS * D_];           // rmsnormed tokens (fp16)
__device__ __half g_qprojh[(size_t)ROWS * 1024];      // x @ Wq (fp16)
__device__ __half g_kvh[(size_t)ROWS * 1024];         // x @ Wkv (fp16)
__device__ __half g_qh[(size_t)B_ * QH_ * N_ * DH_];  // [b][qh][n][dh] fp16
__device__ __half g_kh[(size_t)B_ * H_  * N_ * DH_];  // [b][h][n][dh] fp16
__device__ __half g_vh[(size_t)B_ * H_  * N_ * DH_];  // [b][h][n][dh] fp16
__device__ __half g_oh[(size_t)B_ * QH_ * N_ * DH_];  // per-qhead attn out (fp16)
__device__ __half g_och[(size_t)ROWS * (H_ * DH_)];   // group-summed (fp16)
__device__ __half g_Wqh [(size_t)1024 * 1024];        // fp16 Wq  [k][n]
__device__ __half g_Wkvh[(size_t)1024 * 1024];        // fp16 Wkv [k][n]
__device__ __half g_Woh [(size_t)512 * 1024];         // fp16 Wout[k][n]

// ---------------- helpers ----------------
__device__ __forceinline__ uint32_t smem_u32(const void* p) {
    uint32_t a;
    asm("{ .reg .u64 t; cvta.to.shared.u64 t, %1; cvt.u32.u64 %0, t; }" : "=r"(a) : "l"(p));
    return a;
}
__device__ __forceinline__ uint32_t h2u(__half2 v) {
    uint32_t u;
    memcpy(&u, &v, 4);
    return u;
}
__device__ __forceinline__ void cpa16(uint32_t dst, const void* src) {
    asm volatile("cp.async.ca.shared.global [%0], [%1], 16;" :: "r"(dst), "l"(src));
}
#define CP_COMMIT() asm volatile("cp.async.commit_group;" ::: "memory")
#define CP_WAIT(n)  asm volatile("cp.async.wait_group %0;" :: "n"(n) : "memory")

__device__ __forceinline__ void mmah(float* d, const uint32_t* a, const uint32_t* b) {
    asm volatile("mma.sync.aligned.m16n8k16.row.col.f32.f16.f16.f32 "
                 "{%0,%1,%2,%3}, {%4,%5,%6,%7}, {%8,%9}, {%0,%1,%2,%3};"
                 : "+f"(d[0]), "+f"(d[1]), "+f"(d[2]), "+f"(d[3])
                 : "r"(a[0]), "r"(a[1]), "r"(a[2]), "r"(a[3]),
                   "r"(b[0]), "r"(b[1]));
}
__device__ __forceinline__ void ldsm_x4(uint32_t* r, uint32_t addr) {
    asm volatile("ldmatrix.sync.aligned.m8n8.x4.shared.b16 {%0,%1,%2,%3}, [%4];"
                 : "=r"(r[0]), "=r"(r[1]), "=r"(r[2]), "=r"(r[3]) : "r"(addr));
}
__device__ __forceinline__ void ldsm_x4t(uint32_t* r, uint32_t addr) {
    asm volatile("ldmatrix.sync.aligned.m8n8.x4.trans.shared.b16 {%0,%1,%2,%3}, [%4];"
                 : "=r"(r[0]), "=r"(r[1]), "=r"(r[2]), "=r"(r[3]) : "r"(addr));
}
// P = exp(6.25 * tanh(s/50)) via MUFU.TANH + MUFU.EX2 (2 MUL + 2 MUFU).
__device__ __forceinline__ float softcap_exp(float s) {
    float t;
    asm("tanh.approx.f32 %0, %1;" : "=f"(t) : "f"(s * 0.02f));
    float e;
    asm("ex2.approx.f32 %0, %1;" : "=f"(e) : "f"(t * 9.0168440055f));
    return e;
}
// epilogue store: fp32 or fp16
__device__ __forceinline__ void st2(float* C, size_t off, float x, float y) {
    *(float2*)(C + off) = make_float2(x, y);
}
__device__ __forceinline__ void st2(__half* C, size_t off, float x, float y) {
    *(__half2*)(C + off) = __floats2half2_rn(x, y);
}

// ---------------- 1) fused RMSNorm->fp16 + weight fp32->fp16 ----------------
__global__ __launch_bounds__(256) void k_pre(const float* __restrict__ x,
                                             const float* __restrict__ w,
                                             const float4* __restrict__ Wq,
                                             const float4* __restrict__ Wkv,
                                             const float4* __restrict__ Wo) {
    if (blockIdx.x < 4096) {
        int row = blockIdx.x;
        const float4* xr = (const float4*)(x + (size_t)row * D_);
        float4 xv = xr[threadIdx.x];
        float ss = xv.x*xv.x + xv.y*xv.y + xv.z*xv.z + xv.w*xv.w;
        #pragma unroll
        for (int o = 16; o; o >>= 1) ss += __shfl_xor_sync(0xffffffffu, ss, o);
        __shared__ float sred[8];
        int wid = threadIdx.x >> 5, lid = threadIdx.x & 31;
        if (lid == 0) sred[wid] = ss;
        __syncthreads();
        if (wid == 0) {
            float v = (lid < 8) ? sred[lid] : 0.0f;
            #pragma unroll
            for (int o = 4; o; o >>= 1) v += __shfl_xor_sync(0xffffffffu, v, o);
            if (lid == 0) sred[0] = v;
        }
        __syncthreads();
        float s = rsqrtf(sred[0] * (1.0f / D_) + 1.192092896e-7f);
        float4 wv = ((const float4*)w)[threadIdx.x];
        __half2* dst = (__half2*)(g_xnh + (size_t)row * D_ + threadIdx.x * 4);
        dst[0] = __floats2half2_rn(xv.x * s * wv.x, xv.y * s * wv.y);
        dst[1] = __floats2half2_rn(xv.z * s * wv.z, xv.w * s * wv.w);
    } else {
        int i = (blockIdx.x - 4096) * 256 + threadIdx.x;   // < 655360
        const float4* src; __half2* dst; int j;
        if (i < 262144)      { src = Wq;  dst = (__half2*)g_Wqh;  j = i; }
        else if (i < 524288) { src = Wkv; dst = (__half2*)g_Wkvh; j = i - 262144; }
        else                 { src = Wo;  dst = (__half2*)g_Woh;  j = i - 524288; }
        float4 v = src[j];
        dst[2 * j]     = __floats2half2_rn(v.x, v.y);
        dst[2 * j + 1] = __floats2half2_rn(v.z, v.w);
    }
}

// ---------------- 2) fp16 mma GEMM, 3-stage pipeline, paired x4t B loads ----------------
#define HAS 40
#define HBS 136
#define HASZ (128 * HAS)
#define HBSZ (32 * HBS)
#define HSTG (HASZ + HBSZ)          // 9472 halves / stage
#define GSM  (3 * HSTG * 2)         // 56832 bytes dynamic

template <int NX0, typename T>
__global__ __launch_bounds__(256) void k_gemmh(const __half* __restrict__ A,
                                               const __half* __restrict__ W0,
                                               const __half* __restrict__ W1,
                                               T* __restrict__ C0,
                                               T* __restrict__ C1, int K) {
    extern __shared__ __half hs[];
    const int t = threadIdx.x, wid = t >> 5, lane = t & 31;
    const int wm = wid >> 2, wn = wid & 3;
    const int r = lane >> 2, cq = lane & 3;
    const int m0 = blockIdx.y * 128;
    const __half* W; T* C; int n0;
    if ((int)blockIdx.x < NX0) { W = W0; C = C0; n0 = blockIdx.x * 128; }
    else                       { W = W1; C = C1; n0 = (blockIdx.x - NX0) * 128; }
    const uint32_t sb = smem_u32(hs);

    const int qa0 = t, qa1 = t + 256;
    const int ar0 = qa0 >> 2, ac0 = (qa0 & 3) * 8;
    const int ar1 = qa1 >> 2, ac1 = (qa1 & 3) * 8;
    const int br0 = qa0 >> 4, bc0 = (qa0 & 15) * 8;
    const int br1 = qa1 >> 4, bc1 = (qa1 & 15) * 8;

    const int lrow = lane & 7, lt = lane >> 3;
    const int aR = (lt & 1) * 8 + lrow;
    const int aC = (lt >> 1) * 8;
    const int pn = lt >> 1, pb = (lt & 1) * 8;   // paired-x4t B geometry

    float d[4][4][4];
    #pragma unroll
    for (int i = 0; i < 4; i++)
        #pragma unroll
        for (int j = 0; j < 4; j++)
            #pragma unroll
            for (int v = 0; v < 4; v++) d[i][j][v] = 0.0f;

    const int nc = K >> 5;

    #define LOAD_STAGE(s, c) do { \
        uint32_t ab = sb + (s) * (HSTG * 2); \
        uint32_t bb = ab + HASZ * 2; \
        int k0 = (c) << 5; \
        cpa16(ab + (ar0 * HAS + ac0) * 2, A + (size_t)(m0 + ar0) * K + k0 + ac0); \
        cpa16(ab + (ar1 * HAS + ac1) * 2, A + (size_t)(m0 + ar1) * K + k0 + ac1); \
        cpa16(bb + (br0 * HBS + bc0) * 2, W + (size_t)(k0 + br0) * 1024 + n0 + bc0); \
        cpa16(bb + (br1 * HBS + bc1) * 2, W + (size_t)(k0 + br1) * 1024 + n0 + bc1); \
        CP_COMMIT(); \
    } while (0)

    LOAD_STAGE(0, 0);
    LOAD_STAGE(1, 1);

    for (int c = 0; c < nc; c++) {
        if (c == nc - 1) { CP_WAIT(0); } else { CP_WAIT(1); }
        __syncthreads();
        if (c + 2 < nc) LOAD_STAGE((c + 2) % 3, c + 2);

        uint32_t ab = sb + (c % 3) * (HSTG * 2);
        uint32_t bb = ab + HASZ * 2;
        #pragma unroll
        for (int ks = 0; ks < 2; ks++) {
            uint32_t a[4][4];
            #pragma unroll
            for (int mt = 0; mt < 4; mt++)
                ldsm_x4(a[mt], ab + ((wm * 64 + mt * 16 + aR) * HAS + ks * 16 + aC) * 2);
            #pragma unroll
            for (int np = 0; np < 2; np++) {   // n-tile pair: nt = 2np, 2np+1
                uint32_t b4[4];
                ldsm_x4t(b4, bb + ((ks * 16 + pb + lrow) * HBS +
                                   wn * 32 + (2 * np + pn) * 8) * 2);
                #pragma unroll
                for (int mt = 0; mt < 4; mt++) {
                    mmah(d[mt][2 * np],     a[mt], b4);
                    mmah(d[mt][2 * np + 1], a[mt], b4 + 2);
                }
            }
        }
    }

    #pragma unroll
    for (int mt = 0; mt < 4; mt++) {
        int row = m0 + wm * 64 + mt * 16 + r;
        #pragma unroll
        for (int nt = 0; nt < 4; nt++) {
            int col = n0 + wn * 32 + nt * 8 + 2 * cq;
            st2(C, (size_t)row * 1024 + col, d[mt][nt][0], d[mt][nt][1]);
            st2(C, (size_t)(row + 8) * 1024 + col, d[mt][nt][2], d[mt][nt][3]);
        }
    }
    #undef LOAD_STAGE
}

// ---------------- 3) q/k head norm + v copy: uint4 lanes, 8-lane reduce ----------------
__global__ __launch_bounds__(256) void k_qknorm(const float* __restrict__ q_gamma,
                                                const float* __restrict__ k_gamma) {
    int warp = threadIdx.x >> 5, lane = threadIdx.x & 31;
    int sub = lane >> 3, e8 = (lane & 7) * 8;
    int vec = (blockIdx.x * 8 + warp) * 4 + sub;   // < 98304
    if (vec < 65536) {
        int row = vec >> 4, qh = vec & 15;
        uint4 raw = *(const uint4*)(g_qprojh + (size_t)row * 1024 + qh * 64 + e8);
        __half2 hv[4];
        memcpy(hv, &raw, 16);
        float2 f[4];
        float ss = 0.0f;
        #pragma unroll
        for (int j = 0; j < 4; j++) {
            f[j] = __half22float2(hv[j]);
            ss += f[j].x * f[j].x + f[j].y * f[j].y;
        }
        ss += __shfl_xor_sync(0xffffffffu, ss, 1);
        ss += __shfl_xor_sync(0xffffffffu, ss, 2);
        ss += __shfl_xor_sync(0xffffffffu, ss, 4);
        float inv = 1.0f / fmaxf(sqrtf(ss), 1e-12f);
        float4 g0 = *(const float4*)(q_gamma + qh * 64 + e8);
        float4 g1 = *(const float4*)(q_gamma + qh * 64 + e8 + 4);
        __half2 out[4];
        out[0] = __floats2half2_rn(f[0].x * inv * (g0.x + 1.0f) * 8.0f,
                                   f[0].y * inv * (g0.y + 1.0f) * 8.0f);
        out[1] = __floats2half2_rn(f[1].x * inv * (g0.z + 1.0f) * 8.0f,
                                   f[1].y * inv * (g0.w + 1.0f) * 8.0f);
        out[2] = __floats2half2_rn(f[2].x * inv * (g1.x + 1.0f) * 8.0f,
                                   f[2].y * inv * (g1.y + 1.0f) * 8.0f);
        out[3] = __floats2half2_rn(f[3].x * inv * (g1.z + 1.0f) * 8.0f,
                                   f[3].y * inv * (g1.w + 1.0f) * 8.0f);
        int b = row >> 11, n = row & 2047;
        uint4 packed;
        memcpy(&packed, out, 16);
        *(uint4*)(g_qh + ((((size_t)b * QH_ + qh) * N_ + n) * DH_) + e8) = packed;
    } else {
        int v2 = vec - 65536;
        int row = v2 >> 3, h = v2 & 7;
        const __half* base = g_kvh + (size_t)row * 1024 + h * 64 + e8;
        uint4 kraw = *(const uint4*)base;
        uint4 vraw = *(const uint4*)(base + 512);
        __half2 hv[4];
        memcpy(hv, &kraw, 16);
        float2 f[4];
        float ss = 0.0f;
        #pragma unroll
        for (int j = 0; j < 4; j++) {
            f[j] = __half22float2(hv[j]);
            ss += f[j].x * f[j].x + f[j].y * f[j].y;
        }
        ss += __shfl_xor_sync(0xffffffffu, ss, 1);
        ss += __shfl_xor_sync(0xffffffffu, ss, 2);
        ss += __shfl_xor_sync(0xffffffffu, ss, 4);
        float inv = 1.0f / fmaxf(sqrtf(ss), 1e-12f);
        float4 g0 = *(const float4*)(k_gamma + h * 64 + e8);
        float4 g1 = *(const float4*)(k_gamma + h * 64 + e8 + 4);
        __half2 out[4];
        out[0] = __floats2half2_rn(f[0].x * inv * (g0.x + 1.0f) * 8.0f,
                                   f[0].y * inv * (g0.y + 1.0f) * 8.0f);
        out[1] = __floats2half2_rn(f[1].x * inv * (g0.z + 1.0f) * 8.0f,
                                   f[1].y * inv * (g0.w + 1.0f) * 8.0f);
        out[2] = __floats2half2_rn(f[2].x * inv * (g1.x + 1.0f) * 8.0f,
                                   f[2].y * inv * (g1.y + 1.0f) * 8.0f);
        out[3] = __floats2half2_rn(f[3].x * inv * (g1.z + 1.0f) * 8.0f,
                                   f[3].y * inv * (g1.w + 1.0f) * 8.0f);
        int b = row >> 11, n = row & 2047;
        size_t dst = (((size_t)b * H_ + h) * N_ + n) * DH_ + e8;
        uint4 packed;
        memcpy(&packed, out, 16);
        *(uint4*)(g_kh + dst) = packed;
        *(uint4*)(g_vh + dst) = vraw;
    }
}

// ---------------- 4) causal attention (R15 winner: 16x64/warp, ones-mma sums) ----------------
#define AQS 72
#define T46 4608
#define ATT3_SMEM (4 * T46 * 2)

__global__ __launch_bounds__(128) void k_attn3() {
    extern __shared__ __half sh[];
    const uint32_t sb = smem_u32(sh);

    int bqh = blockIdx.y;                       // b*16 + qh
    int it  = gridDim.x - 1 - blockIdx.x;       // biggest tiles first
    int b = bqh >> 4, qh = bqh & 15, h = qh >> 1;

    const __half* Qg = g_qh + (((size_t)bqh) * N_ + it * 64) * DH_;
    const __half* Kg = g_kh + ((size_t)(b * H_ + h)) * N_ * DH_;
    const __half* Vg = g_vh + ((size_t)(b * H_ + h)) * N_ * DH_;

    const int t = threadIdx.x, wm = t >> 5, lane = t & 31;
    const int r = lane >> 2, cq = lane & 3;
    const int row0 = wm * 16 + r;
    const int lrow = lane & 7, lt = lane >> 3;
    const int aR = (lt & 1) * 8 + lrow, aC = (lt >> 1) * 8;
    const int pn = lt >> 1, pb = (lt & 1) * 8;   // paired-x4 geometry

    // ---- prologue: Q through region 0, hoist fragments ----
    #pragma unroll
    for (int rep = 0; rep < 4; rep++) {
        int slot = rep * 128 + t;
        int i = slot >> 3, d8 = (slot & 7) * 8;
        *(uint4*)&sh[i * AQS + d8] = *(const uint4*)(Qg + i * 64 + d8);
    }
    __syncthreads();
    uint32_t qa[4][4];
    #pragma unroll
    for (int ks = 0; ks < 4; ks++)
        ldsm_x4(qa[ks], sb + ((wm * 16 + aR) * AQS + ks * 16 + aC) * 2);
    __syncthreads();   // all warps done reading Q; region 0 reusable

    // K stage s -> region 2s, V stage s -> region 2s+1
    #define LOADKV(s, jt_) do { \
        uint32_t kb_ = sb + (2 * (s)) * T46 * 2; \
        uint32_t vb_ = sb + (2 * (s) + 1) * T46 * 2; \
        _Pragma("unroll") \
        for (int rep = 0; rep < 4; rep++) { \
            int slot = rep * 128 + t; \
            int j = slot >> 3, d8 = (slot & 7) * 8; \
            cpa16(kb_ + (j * AQS + d8) * 2, Kg + (size_t)((jt_) * 64 + j) * 64 + d8); \
            cpa16(vb_ + (j * AQS + d8) * 2, Vg + (size_t)((jt_) * 64 + j) * 64 + d8); \
        } \
        CP_COMMIT(); \
    } while (0)

    LOADKV(0, 0);

    const uint32_t ONE2 = 0x3C003C00u;          // half2(1,1)
    uint32_t ones[2] = {ONE2, ONE2};

    float o[8][4];
    #pragma unroll
    for (int nt = 0; nt < 8; nt++)
        #pragma unroll
        for (int v = 0; v < 4; v++) o[nt][v] = 0.0f;
    float o9[4] = {0.f, 0.f, 0.f, 0.f};         // row sums via ones-mma

    for (int jt = 0; jt <= it; jt++) {
        int s = jt & 1;
        CP_WAIT(0);
        __syncthreads();       // stage s visible; prior reads of s^1 done
        if (jt < it) LOADKV(s ^ 1, jt + 1);

        uint32_t kb = sb + (2 * s) * T46 * 2;
        uint32_t vb = sb + (2 * s + 1) * T46 * 2;

        // ---- S = Q K^T : paired x4 K loads ----
        float dS[8][4];
        #pragma unroll
        for (int nt = 0; nt < 8; nt++)
            #pragma unroll
            for (int v = 0; v < 4; v++) dS[nt][v] = 0.0f;

        #pragma unroll
        for (int ks = 0; ks < 4; ks++) {
            #pragma unroll
            for (int np = 0; np < 4; np++) {
                uint32_t kr[4];
                ldsm_x4(kr, kb + (((2 * np + pn) * 8 + lrow) * AQS + ks * 16 + pb) * 2);
                mmah(dS[2 * np],     qa[ks], kr);
                mmah(dS[2 * np + 1], qa[ks], kr + 2);
            }
        }

        // ---- softcap+exp+mask -> pack P into PV A-fragments ----
        uint32_t ah[4][4];
        if (jt == it) {
            #pragma unroll
            for (int nt = 0; nt < 8; nt++) {
                int colb = nt * 8 + 2 * cq;
                float p0 = (colb     <= row0)     ? softcap_exp(dS[nt][0]) : 0.0f;
                float p1 = (colb + 1 <= row0)     ? softcap_exp(dS[nt][1]) : 0.0f;
                float p2 = (colb     <= row0 + 8) ? softcap_exp(dS[nt][2]) : 0.0f;
                float p3 = (colb + 1 <= row0 + 8) ? softcap_exp(dS[nt][3]) : 0.0f;
                int c = nt >> 1, hi = (nt & 1) * 2;
                ah[c][hi]     = h2u(__floats2half2_rn(p0, p1));
                ah[c][hi + 1] = h2u(__floats2half2_rn(p2, p3));
            }
        } else {
            #pragma unroll
            for (int nt = 0; nt < 8; nt++) {
                float p0 = softcap_exp(dS[nt][0]);
                float p1 = softcap_exp(dS[nt][1]);
                float p2 = softcap_exp(dS[nt][2]);
                float p3 = softcap_exp(dS[nt][3]);
                int c = nt >> 1, hi = (nt & 1) * 2;
                ah[c][hi]     = h2u(__floats2half2_rn(p0, p1));
                ah[c][hi + 1] = h2u(__floats2half2_rn(p2, p3));
            }
        }

        // ---- O += P V (paired x4t) ; row sums += P * ones ----
        #pragma unroll
        for (int c = 0; c < 4; c++) {
            #pragma unroll
            for (int np = 0; np < 4; np++) {
                uint32_t vr[4];
                ldsm_x4t(vr, vb + ((c * 16 + pb + lrow) * AQS + (2 * np + pn) * 8) * 2);
                mmah(o[2 * np],     ah[c], vr);
                mmah(o[2 * np + 1], ah[c], vr + 2);
            }
            mmah(o9, ah[c], ones);
        }
    }

    float inv  = 1.0f / o9[0];
    float inv8 = 1.0f / o9[2];

    __half* Og = g_oh + (((size_t)bqh) * N_ + it * 64) * DH_;
    #pragma unroll
    for (int nt = 0; nt < 8; nt++) {
        int colb = nt * 8 + 2 * cq;
        *(__half2*)(Og + (size_t)row0 * 64 + colb) =
            __floats2half2_rn(o[nt][0] * inv, o[nt][1] * inv);
        *(__half2*)(Og + (size_t)(row0 + 8) * 64 + colb) =
            __floats2half2_rn(o[nt][2] * inv8, o[nt][3] * inv8);
    }
    #undef LOADKV
}

// ---------------- 5) group-sum combine (fp16 in/out, 8 halves/thread) ----------------
__global__ __launch_bounds__(256) void k_combine() {
    int s8 = blockIdx.x * 256 + threadIdx.x;   // 8-half slot, < 262144
    int col = (s8 & 63) * 8;
    int row = s8 >> 6;
    int h = col >> 6, dh = col & 63;
    int b = row >> 11, n = row & 2047;
    const __half* o1 = g_oh + ((((size_t)b * QH_ + 2 * h) * N_ + n) * DH_ + dh);
    const __half* o2 = o1 + (size_t)N_ * DH_;
    uint4 araw = *(const uint4*)o1, craw = *(const uint4*)o2;
    __half2 a[4], c[4], y[4];
    memcpy(a, &araw, 16);
    memcpy(c, &craw, 16);
    #pragma unroll
    for (int j = 0; j < 4; j++) {
        float2 fa = __half22float2(a[j]), fc = __half22float2(c[j]);
        y[j] = __floats2half2_rn(fa.x + fc.x, fa.y + fc.y);
    }
    uint4 packed;
    memcpy(&packed, y, 16);
    *(uint4*)(g_och + (size_t)row * 512 + col) = packed;
}

// ---------------- launch ----------------
extern "C" void kernel_launch(void* const* d_in, const int* in_sizes, int n_in,
                              void* d_out, int out_size) {
    const float* tokens  = (const float*)d_in[0];
    const float* norm_w  = (const float*)d_in[1];
    const float* Wq      = (const float*)d_in[2];
    const float* Wkv     = (const float*)d_in[3];
    const float* Wout    = (const float*)d_in[4];
    const float* q_gamma = (const float*)d_in[5];
    const float* k_gamma = (const float*)d_in[6];
    float* out = (float*)d_out;

    static __half *Wqh_p = nullptr, *Wkvh_p = nullptr, *Woh_p = nullptr;
    static __half *xnh_p = nullptr, *och_p = nullptr, *qprojh_p = nullptr, *kvh_p = nullptr;
    if (!Wqh_p) {   // first call is the non-captured correctness run
        cudaGetSymbolAddress((void**)&Wqh_p, g_Wqh);
        cudaGetSymbolAddress((void**)&Wkvh_p, g_Wkvh);
        cudaGetSymbolAddress((void**)&Woh_p, g_Woh);
        cudaGetSymbolAddress((void**)&xnh_p, g_xnh);
        cudaGetSymbolAddress((void**)&och_p, g_och);
        cudaGetSymbolAddress((void**)&qprojh_p, g_qprojh);
        cudaGetSymbolAddress((void**)&kvh_p, g_kvh);
        cudaFuncSetAttribute(k_attn3, cudaFuncAttributeMaxDynamicSharedMemorySize, ATT3_SMEM);
        cudaFuncSetAttribute(k_gemmh<8, __half>, cudaFuncAttributeMaxDynamicSharedMemorySize, GSM);
        cudaFuncSetAttribute(k_gemmh<8, float>, cudaFuncAttributeMaxDynamicSharedMemorySize, GSM);
    }

    k_pre<<<6656, 256>>>(tokens, norm_w, (const float4*)Wq,
                         (const float4*)Wkv, (const float4*)Wout);
    k_gemmh<8, __half><<<dim3(16, 32), 256, GSM>>>(xnh_p, Wqh_p, Wkvh_p, qprojh_p, kvh_p, 1024);
    k_qknorm<<<3072, 256>>>(q_gamma, k_gamma);
    k_attn3<<<dim3(32, 32), 128, ATT3_SMEM>>>();
    k_combine<<<1024, 256>>>();
    k_gemmh<8, float><<<dim3(8, 32), 256, GSM>>>(och_p, Woh_p, Woh_p, out, out, 512);
}